// round 7
// baseline (speedup 1.0000x reference)
#include <cuda_runtime.h>
#include <cuda_bf16.h>
#include <math.h>
#include <stdint.h>

// ---------------- problem constants ----------------
#define S      2048
#define DM     1024
#define H      16
#define DH     64
#define DMLP   4096
#define NV     50257
#define NVP    50304      // NV padded to multiple of 64
#define L      2
#define QKVN   (3*DM)     // 3072
#define KH_DM  (DM/2)     // 512
#define KH_MLP (DMLP/2)   // 2048

// ---------------- static scratch ----------------
__device__ float g_resid[S*DM];
__device__ float g_qkv[S*QKVN];
__device__ float g_post[S*DMLP];
__device__ float g_bqkv[L*QKVN];

// packed activation planes [M][K/2] (u32 = bf16 pair: low16 = even k)
__device__ uint32_t a_x_h[S*KH_DM],  a_x_l[S*KH_DM];
__device__ uint32_t a_z_h[S*KH_DM],  a_z_l[S*KH_DM];
__device__ uint32_t a_p_h[S*KH_MLP], a_p_l[S*KH_MLP];

// packed weight planes, TRANSPOSED: [N][K/2] (k contiguous)
__device__ uint32_t wqkv_h[L*QKVN*KH_DM], wqkv_l[L*QKVN*KH_DM];
__device__ uint32_t wo_h  [L*DM*KH_DM],   wo_l  [L*DM*KH_DM];
__device__ uint32_t wi_h  [L*DMLP*KH_DM], wi_l  [L*DMLP*KH_DM];
__device__ uint32_t wu2_h [L*DM*KH_MLP],  wu2_l [L*DM*KH_MLP];
__device__ uint32_t wU_h  [NVP*KH_DM],    wU_l  [NVP*KH_DM];

// ---------------- helpers ----------------
__device__ __forceinline__ void split_pack(float x0, float x1,
                                           uint32_t& hi, uint32_t& lo) {
    __nv_bfloat16 h0 = __float2bfloat16_rn(x0);
    __nv_bfloat16 h1 = __float2bfloat16_rn(x1);
    float r0 = x0 - __bfloat162float(h0);
    float r1 = x1 - __bfloat162float(h1);
    __nv_bfloat16 l0 = __float2bfloat16_rn(r0);
    __nv_bfloat16 l1 = __float2bfloat16_rn(r1);
    __nv_bfloat162 hp = __halves2bfloat162(h0, h1);
    __nv_bfloat162 lp = __halves2bfloat162(l0, l1);
    hi = *reinterpret_cast<uint32_t*>(&hp);
    lo = *reinterpret_cast<uint32_t*>(&lp);
}

__device__ __forceinline__ void mma_bf16(float c[4],
                                         const uint32_t a[4],
                                         uint32_t b0, uint32_t b1) {
    asm volatile(
        "mma.sync.aligned.m16n8k16.row.col.f32.bf16.bf16.f32 "
        "{%0,%1,%2,%3}, {%4,%5,%6,%7}, {%8,%9}, {%0,%1,%2,%3};\n"
        : "+f"(c[0]), "+f"(c[1]), "+f"(c[2]), "+f"(c[3])
        : "r"(a[0]), "r"(a[1]), "r"(a[2]), "r"(a[3]),
          "r"(b0), "r"(b1));
}

__device__ __forceinline__ uint32_t cvta_s(const void* p) {
    return (uint32_t)__cvta_generic_to_shared(p);
}
__device__ __forceinline__ void cpa16(uint32_t dst, const void* src) {
    asm volatile("cp.async.cg.shared.global [%0], [%1], 16;\n"
                 :: "r"(dst), "l"(src) : "memory");
}
#define CP_COMMIT() asm volatile("cp.async.commit_group;\n" ::: "memory")
#define CP_WAIT(n)  asm volatile("cp.async.wait_group %0;\n" :: "n"(n) : "memory")

__device__ __forceinline__ void ldm_x4(uint32_t r[4], const void* p) {
    uint32_t a = cvta_s(p);
    asm volatile("ldmatrix.sync.aligned.m8n8.x4.shared.b16 {%0,%1,%2,%3}, [%4];\n"
                 : "=r"(r[0]), "=r"(r[1]), "=r"(r[2]), "=r"(r[3]) : "r"(a));
}

// f32x2 packed helpers (attention)
__device__ __forceinline__ unsigned long long pk2(float lo, float hi) {
    unsigned long long r;
    asm("mov.b64 %0, {%1,%2};" : "=l"(r) : "f"(lo), "f"(hi));
    return r;
}
__device__ __forceinline__ void unpk2(unsigned long long v, float& lo, float& hi) {
    asm("mov.b64 {%0,%1}, %2;" : "=f"(lo), "=f"(hi) : "l"(v));
}
__device__ __forceinline__ unsigned long long fma2(unsigned long long a,
                                                   unsigned long long b,
                                                   unsigned long long c) {
    unsigned long long r;
    asm("fma.rn.f32x2 %0, %1, %2, %3;" : "=l"(r) : "l"(a), "l"(b), "l"(c));
    return r;
}
__device__ __forceinline__ unsigned long long mul2(unsigned long long a,
                                                   unsigned long long b) {
    unsigned long long r;
    asm("mul.rn.f32x2 %0, %1, %2;" : "=l"(r) : "l"(a), "l"(b));
    return r;
}

// ---------------- embed ----------------
__global__ void embed_kernel(const int* __restrict__ tok,
                             const float* __restrict__ WE,
                             const float* __restrict__ Wpos,
                             float* __restrict__ resid) {
    int i = blockIdx.x * 256 + threadIdx.x;
    if (i >= S*DM) return;
    int s = i >> 10;
    int d = i & (DM-1);
    resid[i] = WE[(size_t)tok[s]*DM + d] + Wpos[i];
}

// ------- weight convert+transpose: float[K][N] -> planes [NP][K/2] -------
__global__ void convert_wt_kernel(const float* __restrict__ W,
                                  uint32_t* __restrict__ Ph,
                                  uint32_t* __restrict__ Pl,
                                  int K, int N, int NP) {
    __shared__ uint32_t Th[32][33], Tl[32][33];
    const int KH = K >> 1;
    int n0  = blockIdx.x * 32;
    int kp0 = blockIdx.y * 32;
    int x = threadIdx.x, y = threadIdx.y;   // 32 x 8
    #pragma unroll
    for (int yy = y; yy < 32; yy += 8) {
        int kp = kp0 + yy, n = n0 + x;
        float v0 = 0.f, v1 = 0.f;
        if (n < N) {
            v0 = W[(size_t)(2*kp)*N + n];
            v1 = W[(size_t)(2*kp + 1)*N + n];
        }
        uint32_t h, l;
        split_pack(v0, v1, h, l);
        Th[yy][x] = h; Tl[yy][x] = l;
    }
    __syncthreads();
    #pragma unroll
    for (int yy = y; yy < 32; yy += 8) {
        int n = n0 + yy, kp = kp0 + x;
        Ph[(size_t)n*KH + kp] = Th[x][yy];
        Pl[(size_t)n*KH + kp] = Tl[x][yy];
    }
}

// -------- pack QKV weights to transposed planes [3*DM][KH_DM] ------------
__global__ void pack_qkv_kernel(const float* __restrict__ WQ,
                                const float* __restrict__ WK,
                                const float* __restrict__ WV,
                                const float* __restrict__ bQ,
                                const float* __restrict__ bK,
                                const float* __restrict__ bV,
                                uint32_t* __restrict__ Wh,
                                uint32_t* __restrict__ Wl,
                                float* __restrict__ bqkv) {
    int idx = blockIdx.x * 256 + threadIdx.x;
    if (idx >= DM*KH_DM) return;
    int c  = idx >> 9;            // output column 0..DM-1 (within each of Q/K/V)
    int kp = idx & (KH_DM-1);     // kpair 0..511
    int h = c >> 6, e = c & (DH-1);
    size_t s0 = ((size_t)h*DM + 2*kp)*DH + e;
    size_t s1 = ((size_t)h*DM + 2*kp + 1)*DH + e;
    uint32_t hh, ll;
    split_pack(WQ[s0], WQ[s1], hh, ll);
    Wh[(size_t)c*KH_DM + kp] = hh;            Wl[(size_t)c*KH_DM + kp] = ll;
    split_pack(WK[s0], WK[s1], hh, ll);
    Wh[(size_t)(DM + c)*KH_DM + kp] = hh;     Wl[(size_t)(DM + c)*KH_DM + kp] = ll;
    split_pack(WV[s0], WV[s1], hh, ll);
    Wh[(size_t)(2*DM + c)*KH_DM + kp] = hh;   Wl[(size_t)(2*DM + c)*KH_DM + kp] = ll;
    if (idx < DM) {
        bqkv[idx]        = bQ[idx];
        bqkv[DM + idx]   = bK[idx];
        bqkv[2*DM + idx] = bV[idx];
    }
}

// ---------------- layernorm -> packed planes ----------------
__global__ void ln_pack_kernel(const float* __restrict__ x,
                               const float* __restrict__ w,
                               const float* __restrict__ b,
                               uint32_t* __restrict__ Ph,
                               uint32_t* __restrict__ Pl) {
    __shared__ float rs[256], rs2[256];
    int r = blockIdx.x, tid = threadIdx.x;
    const float* xr = x + (size_t)r*DM;
    float s = 0.f, s2 = 0.f;
    #pragma unroll
    for (int i = tid; i < DM; i += 256) { float v = xr[i]; s += v; s2 += v*v; }
    rs[tid] = s; rs2[tid] = s2; __syncthreads();
    for (int o = 128; o > 0; o >>= 1) {
        if (tid < o) { rs[tid] += rs[tid+o]; rs2[tid] += rs2[tid+o]; }
        __syncthreads();
    }
    float mu  = rs[0] * (1.f/DM);
    float var = rs2[0] * (1.f/DM) - mu*mu;
    float inv = rsqrtf(var + 1e-5f);
    for (int j = tid; j < KH_DM; j += 256) {
        float y0 = (xr[2*j]   - mu) * inv * w[2*j]   + b[2*j];
        float y1 = (xr[2*j+1] - mu) * inv * w[2*j+1] + b[2*j+1];
        uint32_t h, l;
        split_pack(y0, y1, h, l);
        Ph[(size_t)r*KH_DM + j] = h;
        Pl[(size_t)r*KH_DM + j] = l;
    }
}

// ------- bf16x3 GEMM: ldmatrix fragments, 3-stage cp.async pipeline -------
// A planes [M][K/2] row-major; B planes [N][K/2] (transposed, k contiguous).
// C[M,N] = act(A@B^T + bias) (+R). Grid: (M/128 in x, Ncols/64 in y).
#define NSTG 3
template <int ACT, int PACK>
__global__ __launch_bounds__(256, 2)
void bf16_gemm_kernel(const uint32_t* __restrict__ Ah, const uint32_t* __restrict__ Al,
                      const uint32_t* __restrict__ Bh, const uint32_t* __restrict__ Bl,
                      const float* __restrict__ bias, const float* __restrict__ R,
                      float* __restrict__ C,
                      uint32_t* __restrict__ Ph, uint32_t* __restrict__ Pl,
                      int N, int K) {
    __shared__ __align__(16) uint32_t As[NSTG][2][128][12];  // [stg][plane][m][kp]
    __shared__ __align__(16) uint32_t Bs[NSTG][2][64][12];   // [stg][plane][n][kp]

    const int tid  = threadIdx.x;
    const int lane = tid & 31;
    const int wid  = tid >> 5;
    const int g    = lane >> 2;
    const int t4   = lane & 3;
    const int wm   = wid >> 1;          // 0..3
    const int wn   = wid & 1;           // 0..1
    const int row0 = blockIdx.x * 128;
    const int col0 = blockIdx.y * 64;
    const int KH   = K >> 1;
    const int NIT  = KH >> 3;

    // cp.async staging coords
    const int arow  = tid >> 1;         // 0..127
    const int ahalf = tid & 1;
    const int bpl   = tid >> 7;         // plane
    const int bn    = (tid >> 1) & 63;
    const int bch   = tid & 1;

    // ldmatrix addressing
    const int lr  = lane & 7;
    const int sel = lane >> 3;          // 0..3
    const int aoff = (sel >> 1) * 4;    // k-chunk
    const int arow_f = (sel & 1) * 8 + lr;

    float acc[2][4][4];
    #pragma unroll
    for (int mt = 0; mt < 2; mt++)
        #pragma unroll
        for (int nt = 0; nt < 4; nt++)
            #pragma unroll
            for (int i = 0; i < 4; i++) acc[mt][nt][i] = 0.f;

    auto issue = [&](int kp0, int buf) {
        cpa16(cvta_s(&As[buf][0][arow][ahalf*4]),
              Ah + (size_t)(row0 + arow)*KH + kp0 + ahalf*4);
        cpa16(cvta_s(&As[buf][1][arow][ahalf*4]),
              Al + (size_t)(row0 + arow)*KH + kp0 + ahalf*4);
        const uint32_t* bsrc = (bpl ? Bl : Bh)
            + (size_t)(col0 + bn)*KH + kp0 + bch*4;
        cpa16(cvta_s(&Bs[buf][bpl][bn][bch*4]), bsrc);
    };

    issue(0, 0); CP_COMMIT();
    if (NIT > 1) { issue(8, 1); CP_COMMIT(); }

    for (int it = 0; it < NIT; it++) {
        int cur = it % NSTG;
        if (it + 1 < NIT) { CP_WAIT(1); } else { CP_WAIT(0); }
        __syncthreads();
        if (it + 2 < NIT) { issue((it + 2) * 8, (it + 2) % NSTG); CP_COMMIT(); }

        // ---- fragments via ldmatrix ----
        uint32_t ah[2][4], al[2][4];
        #pragma unroll
        for (int mt = 0; mt < 2; mt++) {
            int rbase = wm*32 + mt*16 + arow_f;
            ldm_x4(ah[mt], &As[cur][0][rbase][aoff]);
            ldm_x4(al[mt], &As[cur][1][rbase][aoff]);
        }
        uint32_t bh0[4], bh1[4], bl0[4], bl1[4];
        {
            int nbase = wn*32 + sel*8 + lr;
            ldm_x4(bh0, &Bs[cur][0][nbase][0]);
            ldm_x4(bh1, &Bs[cur][0][nbase][4]);
            ldm_x4(bl0, &Bs[cur][1][nbase][0]);
            ldm_x4(bl1, &Bs[cur][1][nbase][4]);
        }
        #pragma unroll
        for (int mt = 0; mt < 2; mt++)
            #pragma unroll
            for (int nt = 0; nt < 4; nt++) {
                mma_bf16(acc[mt][nt], ah[mt], bh0[nt], bh1[nt]);  // hi*hi
                mma_bf16(acc[mt][nt], ah[mt], bl0[nt], bl1[nt]);  // hi*lo
                mma_bf16(acc[mt][nt], al[mt], bh0[nt], bh1[nt]);  // lo*hi
            }
    }

    // ---- epilogue ----
    #pragma unroll
    for (int mt = 0; mt < 2; mt++) {
        #pragma unroll
        for (int nt = 0; nt < 4; nt++) {
            float vv[4];
            #pragma unroll
            for (int i = 0; i < 4; i++) {
                int col = col0 + wn*32 + nt*8 + 2*t4 + (i & 1);
                float v = acc[mt][nt][i];
                if (bias && col < N) v += bias[col];
                if (ACT == 1) v = 0.5f * v * (1.f + erff(v * 0.70710678118654752f));
                vv[i] = v;
            }
            #pragma unroll
            for (int i = 0; i < 4; i++) {
                int row = row0 + wm*32 + mt*16 + g + (i >> 1)*8;
                int col = col0 + wn*32 + nt*8 + 2*t4 + (i & 1);
                if (col >= N) continue;
                float v = vv[i];
                if (R) v += R[(size_t)row*N + col];
                C[(size_t)row*N + col] = v;
            }
            if (PACK) {
                int cp = (col0 >> 1) + wn*16 + nt*4 + t4;
                int NH = N >> 1;
                uint32_t h, l;
                int r0p = row0 + wm*32 + mt*16 + g;
                split_pack(vv[0], vv[1], h, l);
                Ph[(size_t)r0p*NH + cp] = h;  Pl[(size_t)r0p*NH + cp] = l;
                split_pack(vv[2], vv[3], h, l);
                Ph[(size_t)(r0p + 8)*NH + cp] = h;  Pl[(size_t)(r0p + 8)*NH + cp] = l;
            }
        }
    }
}

// ---------------- flash attention (packed-z output) ----------------
#define KT 64
__global__ __launch_bounds__(128)
void attn_flash_kernel(const float* __restrict__ qkv,
                       uint32_t* __restrict__ Zh,
                       uint32_t* __restrict__ Zl) {
    const int qt  = (gridDim.x - 1) - blockIdx.x;
    const int h   = blockIdx.y;
    const int tid = threadIdx.x;
    const int q   = qt*128 + tid;
    const int qmax = qt*128 + 127;

    __shared__ unsigned long long Ks[KT][33];
    __shared__ unsigned long long Vs[KT][33];

    unsigned long long qp[32];
    {
        const float4* qrow = reinterpret_cast<const float4*>(
            qkv + (size_t)q*QKVN + h*DH);
        #pragma unroll
        for (int i = 0; i < 16; i++) {
            float4 v = qrow[i];
            qp[2*i]   = pk2(v.x, v.y);
            qp[2*i+1] = pk2(v.z, v.w);
        }
    }
    unsigned long long accp[32];
    #pragma unroll
    for (int i = 0; i < 32; i++) accp[i] = 0ULL;
    float m = -1e30f, lsum = 0.f;

    const int row  = tid >> 1;
    const int half = tid & 1;

    for (int t0 = 0; t0 <= qmax; t0 += KT) {
        __syncthreads();
        {
            const float4* ksrc = reinterpret_cast<const float4*>(
                qkv + (size_t)(t0 + row)*QKVN + DM + h*DH + half*32);
            const float4* vsrc = reinterpret_cast<const float4*>(
                qkv + (size_t)(t0 + row)*QKVN + 2*DM + h*DH + half*32);
            #pragma unroll
            for (int j = 0; j < 8; j++) {
                float4 kv = ksrc[j];
                Ks[row][half*16 + 2*j]     = pk2(kv.x, kv.y);
                Ks[row][half*16 + 2*j + 1] = pk2(kv.z, kv.w);
                float4 vvv = vsrc[j];
                Vs[row][half*16 + 2*j]     = pk2(vvv.x, vvv.y);
                Vs[row][half*16 + 2*j + 1] = pk2(vvv.z, vvv.w);
            }
        }
        __syncthreads();

        int len = q + 1 - t0;
        if (len > KT) len = KT;
        for (int t = 0; t < len; t++) {
            const unsigned long long* kr = Ks[t];
            unsigned long long d0 = 0ULL, d1 = 0ULL, d2 = 0ULL, d3 = 0ULL;
            #pragma unroll
            for (int i = 0; i < 8; i++) {
                d0 = fma2(qp[4*i    ], kr[4*i    ], d0);
                d1 = fma2(qp[4*i + 1], kr[4*i + 1], d1);
                d2 = fma2(qp[4*i + 2], kr[4*i + 2], d2);
                d3 = fma2(qp[4*i + 3], kr[4*i + 3], d3);
            }
            float a0, a1, b0, b1, c0, c1, e0, e1;
            unpk2(d0, a0, a1); unpk2(d1, b0, b1);
            unpk2(d2, c0, c1); unpk2(d3, e0, e1);
            float sc = ((a0 + a1) + (b0 + b1)) + ((c0 + c1) + (e0 + e1));
            sc *= 0.125f;

            float p;
            if (sc > m) {
                float r = __expf(m - sc);
                unsigned long long r2 = pk2(r, r);
                #pragma unroll
                for (int i = 0; i < 32; i++) accp[i] = mul2(accp[i], r2);
                lsum *= r;
                m = sc;
                p = 1.f;
            } else {
                p = __expf(sc - m);
            }
            lsum += p;
            unsigned long long pp = pk2(p, p);
            const unsigned long long* vr = Vs[t];
            #pragma unroll
            for (int i = 0; i < 32; i++)
                accp[i] = fma2(pp, vr[i], accp[i]);
        }
    }

    float inv = 1.f / lsum;
    #pragma unroll
    for (int i = 0; i < 32; i++) {
        float x0, x1;
        unpk2(accp[i], x0, x1);
        uint32_t hh, ll;
        split_pack(x0 * inv, x1 * inv, hh, ll);
        Zh[(size_t)q*KH_DM + h*32 + i] = hh;
        Zl[(size_t)q*KH_DM + h*32 + i] = ll;
    }
}

// ---------------- plain copy ----------------
__global__ void copy_kernel(const float* __restrict__ src, float* __restrict__ dst, int n) {
    int i = blockIdx.x * 256 + threadIdx.x;
    if (i < n) dst[i] = src[i];
}

// ---------------- launcher ----------------
extern "C" void kernel_launch(void* const* d_in, const int* in_sizes, int n_in,
                              void* d_out, int out_size) {
    const int*   tokens = (const int*)  d_in[0];
    const float* W_E    = (const float*)d_in[1];
    const float* W_pos  = (const float*)d_in[2];
    const float* ln1_w  = (const float*)d_in[3];
    const float* ln1_b  = (const float*)d_in[4];
    const float* W_Q    = (const float*)d_in[5];
    const float* b_Q    = (const float*)d_in[6];
    const float* W_K    = (const float*)d_in[7];
    const float* b_K    = (const float*)d_in[8];
    const float* W_V    = (const float*)d_in[9];
    const float* b_V    = (const float*)d_in[10];
    const float* W_O    = (const float*)d_in[11];
    const float* b_O    = (const float*)d_in[12];
    const float* ln2_w  = (const float*)d_in[13];
    const float* ln2_b  = (const float*)d_in[14];
    const float* W_in   = (const float*)d_in[15];
    const float* b_in   = (const float*)d_in[16];
    const float* W_out  = (const float*)d_in[17];
    const float* b_out  = (const float*)d_in[18];
    const float* lnf_w  = (const float*)d_in[19];
    const float* lnf_b  = (const float*)d_in[20];
    const float* W_U    = (const float*)d_in[21];
    const float* b_U    = (const float*)d_in[22];

    float *p_resid, *p_qkv, *p_post, *p_bqkv;
    cudaGetSymbolAddress((void**)&p_resid, g_resid);
    cudaGetSymbolAddress((void**)&p_qkv,   g_qkv);
    cudaGetSymbolAddress((void**)&p_post,  g_post);
    cudaGetSymbolAddress((void**)&p_bqkv,  g_bqkv);

    uint32_t *pxh, *pxl, *pzh, *pzl, *pph, *ppl;
    cudaGetSymbolAddress((void**)&pxh, a_x_h); cudaGetSymbolAddress((void**)&pxl, a_x_l);
    cudaGetSymbolAddress((void**)&pzh, a_z_h); cudaGetSymbolAddress((void**)&pzl, a_z_l);
    cudaGetSymbolAddress((void**)&pph, a_p_h); cudaGetSymbolAddress((void**)&ppl, a_p_l);

    uint32_t *pwqh, *pwql, *pwoh, *pwol, *pwih, *pwil, *pw2h, *pw2l, *pwUh, *pwUl;
    cudaGetSymbolAddress((void**)&pwqh, wqkv_h); cudaGetSymbolAddress((void**)&pwql, wqkv_l);
    cudaGetSymbolAddress((void**)&pwoh, wo_h);   cudaGetSymbolAddress((void**)&pwol, wo_l);
    cudaGetSymbolAddress((void**)&pwih, wi_h);   cudaGetSymbolAddress((void**)&pwil, wi_l);
    cudaGetSymbolAddress((void**)&pw2h, wu2_h);  cudaGetSymbolAddress((void**)&pw2l, wu2_l);
    cudaGetSymbolAddress((void**)&pwUh, wU_h);   cudaGetSymbolAddress((void**)&pwUl, wU_l);

    float* out = (float*)d_out;
    dim3 tb(32, 8);

    embed_kernel<<<(S*DM + 255)/256, 256>>>(tokens, W_E, W_pos, p_resid);

    // ---- weight conversion (per launch) ----
    for (int l = 0; l < L; l++) {
        pack_qkv_kernel<<<(DM*KH_DM + 255)/256, 256>>>(
            W_Q + (size_t)l*H*DM*DH, W_K + (size_t)l*H*DM*DH, W_V + (size_t)l*H*DM*DH,
            b_Q + (size_t)l*H*DH, b_K + (size_t)l*H*DH, b_V + (size_t)l*H*DH,
            pwqh + (size_t)l*QKVN*KH_DM, pwql + (size_t)l*QKVN*KH_DM,
            p_bqkv + (size_t)l*QKVN);
        convert_wt_kernel<<<dim3(DM/32, KH_DM/32), tb>>>(
            W_O + (size_t)l*H*DH*DM,
            pwoh + (size_t)l*DM*KH_DM, pwol + (size_t)l*DM*KH_DM, DM, DM, DM);
        convert_wt_kernel<<<dim3(DMLP/32, KH_DM/32), tb>>>(
            W_in + (size_t)l*DM*DMLP,
            pwih + (size_t)l*DMLP*KH_DM, pwil + (size_t)l*DMLP*KH_DM, DM, DMLP, DMLP);
        convert_wt_kernel<<<dim3(DM/32, KH_MLP/32), tb>>>(
            W_out + (size_t)l*DMLP*DM,
            pw2h + (size_t)l*DM*KH_MLP, pw2l + (size_t)l*DM*KH_MLP, DMLP, DM, DM);
    }
    convert_wt_kernel<<<dim3(NVP/32, KH_DM/32), tb>>>(W_U, pwUh, pwUl, DM, NV, NVP);

    for (int l = 0; l < L; l++) {
        const float* bo  = b_O   + (size_t)l*DM;
        const float* l1w = ln1_w + (size_t)l*DM, *l1b = ln1_b + (size_t)l*DM;
        const float* l2w = ln2_w + (size_t)l*DM, *l2b = ln2_b + (size_t)l*DM;
        const float* bi  = b_in  + (size_t)l*DMLP;
        const float* bo2 = b_out + (size_t)l*DM;

        ln_pack_kernel<<<S, 256>>>(p_resid, l1w, l1b, pxh, pxl);

        // qkv = x @ wqkv + bqkv
        bf16_gemm_kernel<0,0><<<dim3(S/128, QKVN/64), 256>>>(
            pxh, pxl, pwqh + (size_t)l*QKVN*KH_DM, pwql + (size_t)l*QKVN*KH_DM,
            p_bqkv + (size_t)l*QKVN, nullptr, p_qkv, nullptr, nullptr,
            QKVN, DM);

        attn_flash_kernel<<<dim3(S/128, H), 128>>>(p_qkv, pzh, pzl);

        // resid += z @ W_O + b_O
        bf16_gemm_kernel<0,0><<<dim3(S/128, DM/64), 256>>>(
            pzh, pzl, pwoh + (size_t)l*DM*KH_DM, pwol + (size_t)l*DM*KH_DM,
            bo, p_resid, p_resid, nullptr, nullptr, DM, DM);

        ln_pack_kernel<<<S, 256>>>(p_resid, l2w, l2b, pxh, pxl);

        // post = gelu(x @ W_in + b_in)  (float + packed planes)
        bf16_gemm_kernel<1,1><<<dim3(S/128, DMLP/64), 256>>>(
            pxh, pxl, pwih + (size_t)l*DMLP*KH_DM, pwil + (size_t)l*DMLP*KH_DM,
            bi, nullptr, p_post, pph, ppl, DMLP, DM);

        // resid += post @ W_out + b_out
        bf16_gemm_kernel<0,0><<<dim3(S/128, DM/64), 256>>>(
            pph, ppl, pw2h + (size_t)l*DM*KH_MLP, pw2l + (size_t)l*DM*KH_MLP,
            bo2, p_resid, p_resid, nullptr, nullptr, DM, DMLP);
    }

    ln_pack_kernel<<<S, 256>>>(p_resid, lnf_w, lnf_b, pxh, pxl);
    bf16_gemm_kernel<0,0><<<dim3(S/128, NVP/64), 256>>>(
        pxh, pxl, pwUh, pwUl, b_U, nullptr, out, nullptr, nullptr,
        NV, DM);

    const long long LOG_N  = (long long)S * NV;
    const long long RES_N  = (long long)S * DM;
    const long long POST_N = (long long)S * DMLP;
    long long osz = (long long)out_size;
    if (osz >= LOG_N + RES_N)
        copy_kernel<<<(int)((RES_N + 255)/256), 256>>>(p_resid, out + LOG_N, (int)RES_N);
    if (osz >= LOG_N + RES_N + POST_N)
        copy_kernel<<<(int)((POST_N + 255)/256), 256>>>(p_post, out + LOG_N + RES_N, (int)POST_N);
}

// round 10
// speedup vs baseline: 1.2519x; 1.2519x over previous
#include <cuda_runtime.h>
#include <cuda_bf16.h>
#include <math.h>
#include <stdint.h>

// ---------------- problem constants ----------------
#define S      2048
#define DM     1024
#define H      16
#define DH     64
#define DMLP   4096
#define NV     50257
#define NVP    50304      // NV padded to multiple of 128
#define L      2
#define QKVN   (3*DM)     // 3072
#define KH_DM  (DM/2)     // 512
#define KH_MLP (DMLP/2)   // 2048

// ---------------- static scratch ----------------
__device__ float g_resid[S*DM];
__device__ float g_qkv[S*QKVN];
__device__ float g_post[S*DMLP];
__device__ float g_bqkv[L*QKVN];

// packed activation planes (k-pair uint32: low16 = bf16(even k))
__device__ uint32_t a_x_h[S*KH_DM],  a_x_l[S*KH_DM];
__device__ uint32_t a_z_h[S*KH_DM],  a_z_l[S*KH_DM];
__device__ uint32_t a_p_h[S*KH_MLP], a_p_l[S*KH_MLP];

// packed weight planes [K/2][N]
__device__ uint32_t wqkv_h[L*KH_DM*QKVN], wqkv_l[L*KH_DM*QKVN];
__device__ uint32_t wo_h  [L*KH_DM*DM],   wo_l  [L*KH_DM*DM];
__device__ uint32_t wi_h  [L*KH_DM*DMLP], wi_l  [L*KH_DM*DMLP];
__device__ uint32_t wu2_h [L*KH_MLP*DM],  wu2_l [L*KH_MLP*DM];
__device__ uint32_t wU_h  [KH_DM*NVP],    wU_l  [KH_DM*NVP];

// ---------------- helpers ----------------
__device__ __forceinline__ void split_pack(float x0, float x1,
                                           uint32_t& hi, uint32_t& lo) {
    __nv_bfloat16 h0 = __float2bfloat16_rn(x0);
    __nv_bfloat16 h1 = __float2bfloat16_rn(x1);
    float r0 = x0 - __bfloat162float(h0);
    float r1 = x1 - __bfloat162float(h1);
    __nv_bfloat16 l0 = __float2bfloat16_rn(r0);
    __nv_bfloat16 l1 = __float2bfloat16_rn(r1);
    __nv_bfloat162 hp = __halves2bfloat162(h0, h1);
    __nv_bfloat162 lp = __halves2bfloat162(l0, l1);
    hi = *reinterpret_cast<uint32_t*>(&hp);
    lo = *reinterpret_cast<uint32_t*>(&lp);
}

__device__ __forceinline__ void mma_bf16(float c[4],
                                         const uint32_t a[4],
                                         uint32_t b0, uint32_t b1) {
    asm volatile(
        "mma.sync.aligned.m16n8k16.row.col.f32.bf16.bf16.f32 "
        "{%0,%1,%2,%3}, {%4,%5,%6,%7}, {%8,%9}, {%0,%1,%2,%3};\n"
        : "+f"(c[0]), "+f"(c[1]), "+f"(c[2]), "+f"(c[3])
        : "r"(a[0]), "r"(a[1]), "r"(a[2]), "r"(a[3]),
          "r"(b0), "r"(b1));
}

__device__ __forceinline__ uint32_t cvta_s(const void* p) {
    return (uint32_t)__cvta_generic_to_shared(p);
}
__device__ __forceinline__ void cpa16(uint32_t dst, const void* src) {
    asm volatile("cp.async.cg.shared.global [%0], [%1], 16;\n"
                 :: "r"(dst), "l"(src) : "memory");
}
#define CP_COMMIT() asm volatile("cp.async.commit_group;\n" ::: "memory")
#define CP_WAIT(n)  asm volatile("cp.async.wait_group %0;\n" :: "n"(n) : "memory")

// f32x2 packed helpers (attention)
__device__ __forceinline__ unsigned long long pk2(float lo, float hi) {
    unsigned long long r;
    asm("mov.b64 %0, {%1,%2};" : "=l"(r) : "f"(lo), "f"(hi));
    return r;
}
__device__ __forceinline__ void unpk2(unsigned long long v, float& lo, float& hi) {
    asm("mov.b64 {%0,%1}, %2;" : "=f"(lo), "=f"(hi) : "l"(v));
}
__device__ __forceinline__ unsigned long long fma2(unsigned long long a,
                                                   unsigned long long b,
                                                   unsigned long long c) {
    unsigned long long r;
    asm("fma.rn.f32x2 %0, %1, %2, %3;" : "=l"(r) : "l"(a), "l"(b), "l"(c));
    return r;
}
__device__ __forceinline__ unsigned long long mul2(unsigned long long a,
                                                   unsigned long long b) {
    unsigned long long r;
    asm("mul.rn.f32x2 %0, %1, %2;" : "=l"(r) : "l"(a), "l"(b));
    return r;
}

// ---------------- embed ----------------
__global__ void embed_kernel(const int* __restrict__ tok,
                             const float* __restrict__ WE,
                             const float* __restrict__ Wpos,
                             float* __restrict__ resid) {
    int i = blockIdx.x * 256 + threadIdx.x;
    if (i >= S*DM) return;
    int s = i >> 10;
    int d = i & (DM-1);
    resid[i] = WE[(size_t)tok[s]*DM + d] + Wpos[i];
}

// ---------------- weight conversion: float[K][N] -> planes [K/2][NP] ------
__global__ void convert_w_kernel(const float* __restrict__ W,
                                 uint32_t* __restrict__ Ph,
                                 uint32_t* __restrict__ Pl,
                                 int K, int N, int NP) {
    long long i = (long long)blockIdx.x * 256 + threadIdx.x;
    long long tot = (long long)(K >> 1) * NP;
    if (i >= tot) return;
    int n = (int)(i % NP);
    long long kp = i / NP;
    float v0 = 0.f, v1 = 0.f;
    if (n < N) {
        v0 = W[(size_t)(2*kp)*N + n];
        v1 = W[(size_t)(2*kp + 1)*N + n];
    }
    uint32_t h, l;
    split_pack(v0, v1, h, l);
    Ph[i] = h; Pl[i] = l;
}

// ---------------- pack QKV weights directly to planes --------------------
__global__ void pack_qkv_kernel(const float* __restrict__ WQ,
                                const float* __restrict__ WK,
                                const float* __restrict__ WV,
                                const float* __restrict__ bQ,
                                const float* __restrict__ bK,
                                const float* __restrict__ bV,
                                uint32_t* __restrict__ Wh,
                                uint32_t* __restrict__ Wl,
                                float* __restrict__ bqkv) {
    int idx = blockIdx.x * 256 + threadIdx.x;
    if (idx >= KH_DM*DM) return;
    int kp = idx >> 10;
    int c  = idx & (DM-1);
    int h = c >> 6, e = c & (DH-1);
    size_t s0 = ((size_t)h*DM + 2*kp)*DH + e;
    size_t s1 = ((size_t)h*DM + 2*kp + 1)*DH + e;
    uint32_t hh, ll;
    split_pack(WQ[s0], WQ[s1], hh, ll);
    Wh[(size_t)kp*QKVN + c] = hh;        Wl[(size_t)kp*QKVN + c] = ll;
    split_pack(WK[s0], WK[s1], hh, ll);
    Wh[(size_t)kp*QKVN + DM + c] = hh;   Wl[(size_t)kp*QKVN + DM + c] = ll;
    split_pack(WV[s0], WV[s1], hh, ll);
    Wh[(size_t)kp*QKVN + 2*DM + c] = hh; Wl[(size_t)kp*QKVN + 2*DM + c] = ll;
    if (idx < DM) {
        bqkv[idx]        = bQ[idx];
        bqkv[DM + idx]   = bK[idx];
        bqkv[2*DM + idx] = bV[idx];
    }
}

// ---------------- layernorm -> packed planes ----------------
__global__ void ln_pack_kernel(const float* __restrict__ x,
                               const float* __restrict__ w,
                               const float* __restrict__ b,
                               uint32_t* __restrict__ Ph,
                               uint32_t* __restrict__ Pl) {
    __shared__ float rs[256], rs2[256];
    int r = blockIdx.x, tid = threadIdx.x;
    const float* xr = x + (size_t)r*DM;
    float s = 0.f, s2 = 0.f;
    #pragma unroll
    for (int i = tid; i < DM; i += 256) { float v = xr[i]; s += v; s2 += v*v; }
    rs[tid] = s; rs2[tid] = s2; __syncthreads();
    for (int o = 128; o > 0; o >>= 1) {
        if (tid < o) { rs[tid] += rs[tid+o]; rs2[tid] += rs2[tid+o]; }
        __syncthreads();
    }
    float mu  = rs[0] * (1.f/DM);
    float var = rs2[0] * (1.f/DM) - mu*mu;
    float inv = rsqrtf(var + 1e-5f);
    for (int j = tid; j < KH_DM; j += 256) {
        float y0 = (xr[2*j]   - mu) * inv * w[2*j]   + b[2*j];
        float y1 = (xr[2*j+1] - mu) * inv * w[2*j+1] + b[2*j+1];
        uint32_t h, l;
        split_pack(y0, y1, h, l);
        Ph[(size_t)r*KH_DM + j] = h;
        Pl[(size_t)r*KH_DM + j] = l;
    }
}

// ---------------- bf16x3 GEMM: packed planes, cp.async double-buffer ------
// A planes [M][K/2]; B planes [K/2][NB]. C = act(A@B + bias) (+R).
// NTC: col-tiles per wn-half; BN = 16*NTC (64 or 128).
template <int ACT, int PACK, int NTC>
__global__ __launch_bounds__(256, 2)
void bf16_gemm_kernel(const uint32_t* __restrict__ Ah, const uint32_t* __restrict__ Al,
                      const uint32_t* __restrict__ Bh, const uint32_t* __restrict__ Bl,
                      const float* __restrict__ bias, const float* __restrict__ R,
                      float* __restrict__ C,
                      uint32_t* __restrict__ Ph, uint32_t* __restrict__ Pl,
                      int N, int NB, int K) {
    const int BN = 16*NTC;
    __shared__ uint32_t As[2][2][128][12];         // [buf][plane][m][kp]
    __shared__ uint32_t Bs[2][2][8][16*NTC + 8];   // [buf][plane][kp][n] pad%32==8

    const int tid  = threadIdx.x;
    const int lane = tid & 31;
    const int wid  = tid >> 5;
    const int g    = lane >> 2;
    const int t4   = lane & 3;
    const int wm   = wid >> 1;          // 0..3
    const int wn   = wid & 1;           // 0..1
    const int row0 = blockIdx.y * 128;
    const int col0 = blockIdx.x * BN;
    const int KH   = K >> 1;
    const int NIT  = KH >> 3;

    // staging coords
    const int arow  = tid >> 1;      // 0..127
    const int ahalf = tid & 1;
    const int bpl   = tid >> 7;      // 0/1 plane
    const int bkp   = (tid & 127) >> 4;
    const int bq    = tid & 15;

    float acc[2][NTC][4];
    #pragma unroll
    for (int mt = 0; mt < 2; mt++)
        #pragma unroll
        for (int nt = 0; nt < NTC; nt++)
            #pragma unroll
            for (int i = 0; i < 4; i++) acc[mt][nt][i] = 0.f;

    auto issue = [&](int kp0, int buf) {
        cpa16(cvta_s(&As[buf][0][arow][ahalf*4]),
              Ah + (size_t)(row0 + arow)*KH + kp0 + ahalf*4);
        cpa16(cvta_s(&As[buf][1][arow][ahalf*4]),
              Al + (size_t)(row0 + arow)*KH + kp0 + ahalf*4);
        const uint32_t* bp = (bpl ? Bl : Bh) + (size_t)(kp0 + bkp)*NB + col0 + bq*4;
        cpa16(cvta_s(&Bs[buf][bpl][bkp][bq*4]), bp);
        if (NTC == 8)
            cpa16(cvta_s(&Bs[buf][bpl][bkp][bq*4 + 64]), bp + 64);
    };

    issue(0, 0);
    CP_COMMIT();

    for (int it = 0; it < NIT; it++) {
        int cur = it & 1;
        if (it + 1 < NIT) {
            issue((it + 1) * 8, cur ^ 1);
            CP_COMMIT();
            CP_WAIT(1);
        } else {
            CP_WAIT(0);
        }
        __syncthreads();

        uint32_t ah[2][4], al[2][4];
        #pragma unroll
        for (int mt = 0; mt < 2; mt++) {
            int rb = wm*32 + mt*16;
            ah[mt][0] = As[cur][0][rb + g    ][t4    ];
            ah[mt][1] = As[cur][0][rb + g + 8][t4    ];
            ah[mt][2] = As[cur][0][rb + g    ][t4 + 4];
            ah[mt][3] = As[cur][0][rb + g + 8][t4 + 4];
            al[mt][0] = As[cur][1][rb + g    ][t4    ];
            al[mt][1] = As[cur][1][rb + g + 8][t4    ];
            al[mt][2] = As[cur][1][rb + g    ][t4 + 4];
            al[mt][3] = As[cur][1][rb + g + 8][t4 + 4];
        }
        #pragma unroll
        for (int nt = 0; nt < NTC; nt++) {
            int cb = wn*(NTC*8) + nt*8 + g;
            uint32_t bh0 = Bs[cur][0][t4    ][cb];
            uint32_t bh1 = Bs[cur][0][t4 + 4][cb];
            uint32_t bl0 = Bs[cur][1][t4    ][cb];
            uint32_t bl1 = Bs[cur][1][t4 + 4][cb];
            #pragma unroll
            for (int mt = 0; mt < 2; mt++) {
                mma_bf16(acc[mt][nt], ah[mt], bh0, bh1);   // hi*hi
                mma_bf16(acc[mt][nt], ah[mt], bl0, bl1);   // hi*lo
                mma_bf16(acc[mt][nt], al[mt], bh0, bh1);   // lo*hi
            }
        }
        __syncthreads();
    }

    // ---- epilogue ----
    #pragma unroll
    for (int mt = 0; mt < 2; mt++) {
        #pragma unroll
        for (int nt = 0; nt < NTC; nt++) {
            float vv[4];
            #pragma unroll
            for (int i = 0; i < 4; i++) {
                int col = col0 + wn*(NTC*8) + nt*8 + 2*t4 + (i & 1);
                float v = acc[mt][nt][i];
                if (bias && col < N) v += bias[col];
                if (ACT == 1) v = 0.5f * v * (1.f + erff(v * 0.70710678118654752f));
                vv[i] = v;
            }
            #pragma unroll
            for (int i = 0; i < 4; i++) {
                int row = row0 + wm*32 + mt*16 + g + (i >> 1)*8;
                int col = col0 + wn*(NTC*8) + nt*8 + 2*t4 + (i & 1);
                if (col >= N) continue;
                float v = vv[i];
                if (R) v += R[(size_t)row*N + col];
                C[(size_t)row*N + col] = v;
            }
            if (PACK) {
                int cp = (col0 >> 1) + wn*(NTC*4) + nt*4 + t4;
                int NH = N >> 1;
                uint32_t h, l;
                int r0p = row0 + wm*32 + mt*16 + g;
                split_pack(vv[0], vv[1], h, l);
                Ph[(size_t)r0p*NH + cp] = h;  Pl[(size_t)r0p*NH + cp] = l;
                split_pack(vv[2], vv[3], h, l);
                Ph[(size_t)(r0p + 8)*NH + cp] = h;  Pl[(size_t)(r0p + 8)*NH + cp] = l;
            }
        }
    }
}

// ---------------- flash attention (packed-z output) ----------------
#define KT 64
__global__ __launch_bounds__(128)
void attn_flash_kernel(const float* __restrict__ qkv,
                       uint32_t* __restrict__ Zh,
                       uint32_t* __restrict__ Zl) {
    const int qt  = (gridDim.x - 1) - blockIdx.x;
    const int h   = blockIdx.y;
    const int tid = threadIdx.x;
    const int q   = qt*128 + tid;
    const int qmax = qt*128 + 127;

    __shared__ unsigned long long Ks[KT][33];
    __shared__ unsigned long long Vs[KT][33];

    unsigned long long qp[32];
    {
        const float4* qrow = reinterpret_cast<const float4*>(
            qkv + (size_t)q*QKVN + h*DH);
        #pragma unroll
        for (int i = 0; i < 16; i++) {
            float4 v = qrow[i];
            qp[2*i]   = pk2(v.x, v.y);
            qp[2*i+1] = pk2(v.z, v.w);
        }
    }
    unsigned long long accp[32];
    #pragma unroll
    for (int i = 0; i < 32; i++) accp[i] = 0ULL;
    float m = -1e30f, lsum = 0.f;

    const int row  = tid >> 1;
    const int half = tid & 1;

    for (int t0 = 0; t0 <= qmax; t0 += KT) {
        __syncthreads();
        {
            const float4* ksrc = reinterpret_cast<const float4*>(
                qkv + (size_t)(t0 + row)*QKVN + DM + h*DH + half*32);
            const float4* vsrc = reinterpret_cast<const float4*>(
                qkv + (size_t)(t0 + row)*QKVN + 2*DM + h*DH + half*32);
            #pragma unroll
            for (int j = 0; j < 8; j++) {
                float4 kv = ksrc[j];
                Ks[row][half*16 + 2*j]     = pk2(kv.x, kv.y);
                Ks[row][half*16 + 2*j + 1] = pk2(kv.z, kv.w);
                float4 vvv = vsrc[j];
                Vs[row][half*16 + 2*j]     = pk2(vvv.x, vvv.y);
                Vs[row][half*16 + 2*j + 1] = pk2(vvv.z, vvv.w);
            }
        }
        __syncthreads();

        int len = q + 1 - t0;
        if (len > KT) len = KT;
        for (int t = 0; t < len; t++) {
            const unsigned long long* kr = Ks[t];
            unsigned long long d0 = 0ULL, d1 = 0ULL, d2 = 0ULL, d3 = 0ULL;
            #pragma unroll
            for (int i = 0; i < 8; i++) {
                d0 = fma2(qp[4*i    ], kr[4*i    ], d0);
                d1 = fma2(qp[4*i + 1], kr[4*i + 1], d1);
                d2 = fma2(qp[4*i + 2], kr[4*i + 2], d2);
                d3 = fma2(qp[4*i + 3], kr[4*i + 3], d3);
            }
            float a0, a1, b0, b1, c0, c1, e0, e1;
            unpk2(d0, a0, a1); unpk2(d1, b0, b1);
            unpk2(d2, c0, c1); unpk2(d3, e0, e1);
            float sc = ((a0 + a1) + (b0 + b1)) + ((c0 + c1) + (e0 + e1));
            sc *= 0.125f;

            float p;
            if (sc > m) {
                float r = __expf(m - sc);
                unsigned long long r2 = pk2(r, r);
                #pragma unroll
                for (int i = 0; i < 32; i++) accp[i] = mul2(accp[i], r2);
                lsum *= r;
                m = sc;
                p = 1.f;
            } else {
                p = __expf(sc - m);
            }
            lsum += p;
            unsigned long long pp = pk2(p, p);
            const unsigned long long* vr = Vs[t];
            #pragma unroll
            for (int i = 0; i < 32; i++)
                accp[i] = fma2(pp, vr[i], accp[i]);
        }
    }

    float inv = 1.f / lsum;
    #pragma unroll
    for (int i = 0; i < 32; i++) {
        float x0, x1;
        unpk2(accp[i], x0, x1);
        uint32_t hh, ll;
        split_pack(x0 * inv, x1 * inv, hh, ll);
        Zh[(size_t)q*KH_DM + h*32 + i] = hh;
        Zl[(size_t)q*KH_DM + h*32 + i] = ll;
    }
}

// ---------------- plain copy ----------------
__global__ void copy_kernel(const float* __restrict__ src, float* __restrict__ dst, int n) {
    int i = blockIdx.x * 256 + threadIdx.x;
    if (i < n) dst[i] = src[i];
}

// ---------------- launcher ----------------
extern "C" void kernel_launch(void* const* d_in, const int* in_sizes, int n_in,
                              void* d_out, int out_size) {
    const int*   tokens = (const int*)  d_in[0];
    const float* W_E    = (const float*)d_in[1];
    const float* W_pos  = (const float*)d_in[2];
    const float* ln1_w  = (const float*)d_in[3];
    const float* ln1_b  = (const float*)d_in[4];
    const float* W_Q    = (const float*)d_in[5];
    const float* b_Q    = (const float*)d_in[6];
    const float* W_K    = (const float*)d_in[7];
    const float* b_K    = (const float*)d_in[8];
    const float* W_V    = (const float*)d_in[9];
    const float* b_V    = (const float*)d_in[10];
    const float* W_O    = (const float*)d_in[11];
    const float* b_O    = (const float*)d_in[12];
    const float* ln2_w  = (const float*)d_in[13];
    const float* ln2_b  = (const float*)d_in[14];
    const float* W_in   = (const float*)d_in[15];
    const float* b_in   = (const float*)d_in[16];
    const float* W_out  = (const float*)d_in[17];
    const float* b_out  = (const float*)d_in[18];
    const float* lnf_w  = (const float*)d_in[19];
    const float* lnf_b  = (const float*)d_in[20];
    const float* W_U    = (const float*)d_in[21];
    const float* b_U    = (const float*)d_in[22];

    float *p_resid, *p_qkv, *p_post, *p_bqkv;
    cudaGetSymbolAddress((void**)&p_resid, g_resid);
    cudaGetSymbolAddress((void**)&p_qkv,   g_qkv);
    cudaGetSymbolAddress((void**)&p_post,  g_post);
    cudaGetSymbolAddress((void**)&p_bqkv,  g_bqkv);

    uint32_t *pxh, *pxl, *pzh, *pzl, *pph, *ppl;
    cudaGetSymbolAddress((void**)&pxh, a_x_h); cudaGetSymbolAddress((void**)&pxl, a_x_l);
    cudaGetSymbolAddress((void**)&pzh, a_z_h); cudaGetSymbolAddress((void**)&pzl, a_z_l);
    cudaGetSymbolAddress((void**)&pph, a_p_h); cudaGetSymbolAddress((void**)&ppl, a_p_l);

    uint32_t *pwqh, *pwql, *pwoh, *pwol, *pwih, *pwil, *pw2h, *pw2l, *pwUh, *pwUl;
    cudaGetSymbolAddress((void**)&pwqh, wqkv_h); cudaGetSymbolAddress((void**)&pwql, wqkv_l);
    cudaGetSymbolAddress((void**)&pwoh, wo_h);   cudaGetSymbolAddress((void**)&pwol, wo_l);
    cudaGetSymbolAddress((void**)&pwih, wi_h);   cudaGetSymbolAddress((void**)&pwil, wi_l);
    cudaGetSymbolAddress((void**)&pw2h, wu2_h);  cudaGetSymbolAddress((void**)&pw2l, wu2_l);
    cudaGetSymbolAddress((void**)&pwUh, wU_h);   cudaGetSymbolAddress((void**)&pwUl, wU_l);

    float* out = (float*)d_out;

    embed_kernel<<<(S*DM + 255)/256, 256>>>(tokens, W_E, W_pos, p_resid);

    // ---- one-time weight conversions (per launch) ----
    for (int l = 0; l < L; l++) {
        pack_qkv_kernel<<<(KH_DM*DM + 255)/256, 256>>>(
            W_Q + (size_t)l*H*DM*DH, W_K + (size_t)l*H*DM*DH, W_V + (size_t)l*H*DM*DH,
            b_Q + (size_t)l*H*DH, b_K + (size_t)l*H*DH, b_V + (size_t)l*H*DH,
            pwqh + (size_t)l*KH_DM*QKVN, pwql + (size_t)l*KH_DM*QKVN,
            p_bqkv + (size_t)l*QKVN);
        long long t;
        t = (long long)KH_DM*DM;
        convert_w_kernel<<<(int)((t + 255)/256), 256>>>(
            W_O + (size_t)l*H*DH*DM,
            pwoh + (size_t)l*KH_DM*DM, pwol + (size_t)l*KH_DM*DM, DM, DM, DM);
        t = (long long)KH_DM*DMLP;
        convert_w_kernel<<<(int)((t + 255)/256), 256>>>(
            W_in + (size_t)l*DM*DMLP,
            pwih + (size_t)l*KH_DM*DMLP, pwil + (size_t)l*KH_DM*DMLP, DM, DMLP, DMLP);
        t = (long long)KH_MLP*DM;
        convert_w_kernel<<<(int)((t + 255)/256), 256>>>(
            W_out + (size_t)l*DMLP*DM,
            pw2h + (size_t)l*KH_MLP*DM, pw2l + (size_t)l*KH_MLP*DM, DMLP, DM, DM);
    }
    {
        long long t = (long long)KH_DM*NVP;
        convert_w_kernel<<<(int)((t + 255)/256), 256>>>(W_U, pwUh, pwUl, DM, NV, NVP);
    }

    for (int l = 0; l < L; l++) {
        const float* bo  = b_O   + (size_t)l*DM;
        const float* l1w = ln1_w + (size_t)l*DM, *l1b = ln1_b + (size_t)l*DM;
        const float* l2w = ln2_w + (size_t)l*DM, *l2b = ln2_b + (size_t)l*DM;
        const float* bi  = b_in  + (size_t)l*DMLP;
        const float* bo2 = b_out + (size_t)l*DM;

        ln_pack_kernel<<<S, 256>>>(p_resid, l1w, l1b, pxh, pxl);

        // qkv = x @ wqkv + bqkv   (wide tile)
        bf16_gemm_kernel<0,0,8><<<dim3(QKVN/128, S/128), 256>>>(
            pxh, pxl, pwqh + (size_t)l*KH_DM*QKVN, pwql + (size_t)l*KH_DM*QKVN,
            p_bqkv + (size_t)l*QKVN, nullptr, p_qkv, nullptr, nullptr,
            QKVN, QKVN, DM);

        attn_flash_kernel<<<dim3(S/128, H), 128>>>(p_qkv, pzh, pzl);

        // resid += z @ W_O + b_O   (narrow tile: N=1024 -> 256 blocks)
        bf16_gemm_kernel<0,0,4><<<dim3(DM/64, S/128), 256>>>(
            pzh, pzl, pwoh + (size_t)l*KH_DM*DM, pwol + (size_t)l*KH_DM*DM,
            bo, p_resid, p_resid, nullptr, nullptr, DM, DM, DM);

        ln_pack_kernel<<<S, 256>>>(p_resid, l2w, l2b, pxh, pxl);

        // post = gelu(x @ W_in + b_in)  (wide tile; float + packed planes)
        bf16_gemm_kernel<1,1,8><<<dim3(DMLP/128, S/128), 256>>>(
            pxh, pxl, pwih + (size_t)l*KH_DM*DMLP, pwil + (size_t)l*KH_DM*DMLP,
            bi, nullptr, p_post, pph, ppl, DMLP, DMLP, DM);

        // resid += post @ W_out + b_out  (narrow tile)
        bf16_gemm_kernel<0,0,4><<<dim3(DM/64, S/128), 256>>>(
            pph, ppl, pw2h + (size_t)l*KH_MLP*DM, pw2l + (size_t)l*KH_MLP*DM,
            bo2, p_resid, p_resid, nullptr, nullptr, DM, DM, DMLP);
    }

    ln_pack_kernel<<<S, 256>>>(p_resid, lnf_w, lnf_b, pxh, pxl);
    bf16_gemm_kernel<0,0,8><<<dim3(NVP/128, S/128), 256>>>(
        pxh, pxl, pwUh, pwUl, b_U, nullptr, out, nullptr, nullptr,
        NV, NVP, DM);

    const long long LOG_N  = (long long)S * NV;
    const long long RES_N  = (long long)S * DM;
    const long long POST_N = (long long)S * DMLP;
    long long osz = (long long)out_size;
    if (osz >= LOG_N + RES_N)
        copy_kernel<<<(int)((RES_N + 255)/256), 256>>>(p_resid, out + LOG_N, (int)RES_N);
    if (osz >= LOG_N + RES_N + POST_N)
        copy_kernel<<<(int)((POST_N + 255)/256), 256>>>(p_post, out + LOG_N + RES_N, (int)POST_N);
}

// round 14
// speedup vs baseline: 1.2670x; 1.0121x over previous
#include <cuda_runtime.h>
#include <cuda_bf16.h>
#include <math.h>
#include <stdint.h>

// ---------------- problem constants ----------------
#define S      2048
#define DM     1024
#define H      16
#define DH     64
#define DMLP   4096
#define NV     50257
#define NVP    50304      // NV padded to multiple of 128
#define L      2
#define QKVN   (3*DM)     // 3072
#define KH_DM  (DM/2)     // 512
#define KH_MLP (DMLP/2)   // 2048

// ---------------- static scratch ----------------
__device__ float g_resid[S*DM];
__device__ float g_qkv[S*QKVN];
__device__ float g_post[S*DMLP];
__device__ float g_bqkv[L*QKVN];

// packed activation planes (k-pair uint32: low16 = bf16(even k))
__device__ uint32_t a_x_h[S*KH_DM],  a_x_l[S*KH_DM];
__device__ uint32_t a_z_h[S*KH_DM],  a_z_l[S*KH_DM];
__device__ uint32_t a_p_h[S*KH_MLP], a_p_l[S*KH_MLP];

// packed weight planes [K/2][N]
__device__ uint32_t wqkv_h[L*KH_DM*QKVN], wqkv_l[L*KH_DM*QKVN];
__device__ uint32_t wo_h  [L*KH_DM*DM],   wo_l  [L*KH_DM*DM];
__device__ uint32_t wi_h  [L*KH_DM*DMLP], wi_l  [L*KH_DM*DMLP];
__device__ uint32_t wu2_h [L*KH_MLP*DM],  wu2_l [L*KH_MLP*DM];
__device__ uint32_t wU_h  [(size_t)KH_DM*NVP], wU_l [(size_t)KH_DM*NVP];

// ---------------- helpers ----------------
__device__ __forceinline__ void split_pack(float x0, float x1,
                                           uint32_t& hi, uint32_t& lo) {
    __nv_bfloat16 h0 = __float2bfloat16_rn(x0);
    __nv_bfloat16 h1 = __float2bfloat16_rn(x1);
    float r0 = x0 - __bfloat162float(h0);
    float r1 = x1 - __bfloat162float(h1);
    __nv_bfloat16 l0 = __float2bfloat16_rn(r0);
    __nv_bfloat16 l1 = __float2bfloat16_rn(r1);
    __nv_bfloat162 hp = __halves2bfloat162(h0, h1);
    __nv_bfloat162 lp = __halves2bfloat162(l0, l1);
    hi = *reinterpret_cast<uint32_t*>(&hp);
    lo = *reinterpret_cast<uint32_t*>(&lp);
}

__device__ __forceinline__ void mma_bf16(float c[4],
                                         const uint32_t a[4],
                                         uint32_t b0, uint32_t b1) {
    asm volatile(
        "mma.sync.aligned.m16n8k16.row.col.f32.bf16.bf16.f32 "
        "{%0,%1,%2,%3}, {%4,%5,%6,%7}, {%8,%9}, {%0,%1,%2,%3};\n"
        : "+f"(c[0]), "+f"(c[1]), "+f"(c[2]), "+f"(c[3])
        : "r"(a[0]), "r"(a[1]), "r"(a[2]), "r"(a[3]),
          "r"(b0), "r"(b1));
}

__device__ __forceinline__ uint32_t cvta_s(const void* p) {
    return (uint32_t)__cvta_generic_to_shared(p);
}
__device__ __forceinline__ void cpa16(uint32_t dst, const void* src) {
    asm volatile("cp.async.cg.shared.global [%0], [%1], 16;\n"
                 :: "r"(dst), "l"(src) : "memory");
}
#define CP_COMMIT() asm volatile("cp.async.commit_group;\n" ::: "memory")
#define CP_WAIT(n)  asm volatile("cp.async.wait_group %0;\n" :: "n"(n) : "memory")

// f32x2 packed helpers (attention)
__device__ __forceinline__ unsigned long long pk2(float lo, float hi) {
    unsigned long long r;
    asm("mov.b64 %0, {%1,%2};" : "=l"(r) : "f"(lo), "f"(hi));
    return r;
}
__device__ __forceinline__ void unpk2(unsigned long long v, float& lo, float& hi) {
    asm("mov.b64 {%0,%1}, %2;" : "=f"(lo), "=f"(hi) : "l"(v));
}
__device__ __forceinline__ unsigned long long fma2(unsigned long long a,
                                                   unsigned long long b,
                                                   unsigned long long c) {
    unsigned long long r;
    asm("fma.rn.f32x2 %0, %1, %2, %3;" : "=l"(r) : "l"(a), "l"(b), "l"(c));
    return r;
}
__device__ __forceinline__ unsigned long long mul2(unsigned long long a,
                                                   unsigned long long b) {
    unsigned long long r;
    asm("mul.rn.f32x2 %0, %1, %2;" : "=l"(r) : "l"(a), "l"(b));
    return r;
}

// ---------------- embed ----------------
__global__ void embed_kernel(const int* __restrict__ tok,
                             const float* __restrict__ WE,
                             const float* __restrict__ Wpos,
                             float* __restrict__ resid) {
    int i = blockIdx.x * 256 + threadIdx.x;
    if (i >= S*DM) return;
    int s = i >> 10;
    int d = i & (DM-1);
    resid[i] = WE[(size_t)tok[s]*DM + d] + Wpos[i];
}

// ------ vectorized weight conversion (aligned rows, N % 4 == 0) ----------
// float[K][N] -> planes [K/2][N]; 4 columns per thread, float4/uint4.
__global__ void convert_w4_kernel(const float* __restrict__ W,
                                  uint32_t* __restrict__ Ph,
                                  uint32_t* __restrict__ Pl,
                                  int K, int N) {
    long long i = (long long)blockIdx.x * 256 + threadIdx.x;
    long long tot = (long long)(K >> 1) * (N >> 2);
    if (i >= tot) return;
    int n4 = (int)(i % (N >> 2));
    long long kp = i / (N >> 2);
    float4 a = *reinterpret_cast<const float4*>(&W[(size_t)(2*kp)*N + n4*4]);
    float4 b = *reinterpret_cast<const float4*>(&W[(size_t)(2*kp + 1)*N + n4*4]);
    uint4 h, l;
    split_pack(a.x, b.x, h.x, l.x);
    split_pack(a.y, b.y, h.y, l.y);
    split_pack(a.z, b.z, h.z, l.z);
    split_pack(a.w, b.w, h.w, l.w);
    *reinterpret_cast<uint4*>(&Ph[(size_t)kp*N + n4*4]) = h;
    *reinterpret_cast<uint4*>(&Pl[(size_t)kp*N + n4*4]) = l;
}

// ------ W_U conversion (odd N -> unaligned rows): scalar loads, uint4 stores
__global__ void convert_wu_kernel(const float* __restrict__ W,
                                  uint32_t* __restrict__ Ph,
                                  uint32_t* __restrict__ Pl,
                                  int K, int N, int NP) {
    long long i = (long long)blockIdx.x * 256 + threadIdx.x;
    long long tot = (long long)(K >> 1) * (NP >> 2);
    if (i >= tot) return;
    int n0 = (int)(i % (NP >> 2)) * 4;
    long long kp = i / (NP >> 2);
    const float* r0 = W + (size_t)(2*kp)*N;
    const float* r1 = W + (size_t)(2*kp + 1)*N;
    float a[4], b[4];
    #pragma unroll
    for (int e = 0; e < 4; e++) {
        int n = n0 + e;
        a[e] = (n < N) ? __ldg(r0 + n) : 0.f;
        b[e] = (n < N) ? __ldg(r1 + n) : 0.f;
    }
    uint4 h, l;
    split_pack(a[0], b[0], h.x, l.x);
    split_pack(a[1], b[1], h.y, l.y);
    split_pack(a[2], b[2], h.z, l.z);
    split_pack(a[3], b[3], h.w, l.w);
    *reinterpret_cast<uint4*>(&Ph[(size_t)kp*NP + n0]) = h;
    *reinterpret_cast<uint4*>(&Pl[(size_t)kp*NP + n0]) = l;
}

// ---------------- pack QKV weights directly to planes --------------------
__global__ void pack_qkv_kernel(const float* __restrict__ WQ,
                                const float* __restrict__ WK,
                                const float* __restrict__ WV,
                                const float* __restrict__ bQ,
                                const float* __restrict__ bK,
                                const float* __restrict__ bV,
                                uint32_t* __restrict__ Wh,
                                uint32_t* __restrict__ Wl,
                                float* __restrict__ bqkv) {
    int idx = blockIdx.x * 256 + threadIdx.x;
    if (idx >= KH_DM*DM) return;
    int kp = idx >> 10;
    int c  = idx & (DM-1);
    int h = c >> 6, e = c & (DH-1);
    size_t s0 = ((size_t)h*DM + 2*kp)*DH + e;
    size_t s1 = ((size_t)h*DM + 2*kp + 1)*DH + e;
    uint32_t hh, ll;
    split_pack(WQ[s0], WQ[s1], hh, ll);
    Wh[(size_t)kp*QKVN + c] = hh;        Wl[(size_t)kp*QKVN + c] = ll;
    split_pack(WK[s0], WK[s1], hh, ll);
    Wh[(size_t)kp*QKVN + DM + c] = hh;   Wl[(size_t)kp*QKVN + DM + c] = ll;
    split_pack(WV[s0], WV[s1], hh, ll);
    Wh[(size_t)kp*QKVN + 2*DM + c] = hh; Wl[(size_t)kp*QKVN + 2*DM + c] = ll;
    if (idx < DM) {
        bqkv[idx]        = bQ[idx];
        bqkv[DM + idx]   = bK[idx];
        bqkv[2*DM + idx] = bV[idx];
    }
}

// ---------------- layernorm -> packed planes ----------------
__global__ void ln_pack_kernel(const float* __restrict__ x,
                               const float* __restrict__ w,
                               const float* __restrict__ b,
                               uint32_t* __restrict__ Ph,
                               uint32_t* __restrict__ Pl) {
    __shared__ float rs[256], rs2[256];
    int r = blockIdx.x, tid = threadIdx.x;
    const float* xr = x + (size_t)r*DM;
    float s = 0.f, s2 = 0.f;
    #pragma unroll
    for (int i = tid; i < DM; i += 256) { float v = xr[i]; s += v; s2 += v*v; }
    rs[tid] = s; rs2[tid] = s2; __syncthreads();
    for (int o = 128; o > 0; o >>= 1) {
        if (tid < o) { rs[tid] += rs[tid+o]; rs2[tid] += rs2[tid+o]; }
        __syncthreads();
    }
    float mu  = rs[0] * (1.f/DM);
    float var = rs2[0] * (1.f/DM) - mu*mu;
    float inv = rsqrtf(var + 1e-5f);
    for (int j = tid; j < KH_DM; j += 256) {
        float y0 = (xr[2*j]   - mu) * inv * w[2*j]   + b[2*j];
        float y1 = (xr[2*j+1] - mu) * inv * w[2*j+1] + b[2*j+1];
        uint32_t h, l;
        split_pack(y0, y1, h, l);
        Ph[(size_t)r*KH_DM + j] = h;
        Pl[(size_t)r*KH_DM + j] = l;
    }
}

// ---------------- bf16x3 GEMM: packed planes, cp.async double-buffer ------
// A planes [M][K/2]; B planes [K/2][NB]. C = act(A@B + bias) (+R).
// NTC: col-tiles per wn-half; BN = 16*NTC. SWAP=1: blockIdx.x indexes rows
// (consecutive blocks share a B column tile -> L2 reuse when B > L2).
template <int ACT, int PACK, int NTC, int SWAP>
__global__ __launch_bounds__(256, 2)
void bf16_gemm_kernel(const uint32_t* __restrict__ Ah, const uint32_t* __restrict__ Al,
                      const uint32_t* __restrict__ Bh, const uint32_t* __restrict__ Bl,
                      const float* __restrict__ bias, const float* __restrict__ R,
                      float* __restrict__ C,
                      uint32_t* __restrict__ Ph, uint32_t* __restrict__ Pl,
                      int N, int NB, int K) {
    const int BN = 16*NTC;
    __shared__ uint32_t As[2][2][128][12];
    __shared__ uint32_t Bs[2][2][8][16*NTC + 8];

    const int tid  = threadIdx.x;
    const int lane = tid & 31;
    const int wid  = tid >> 5;
    const int g    = lane >> 2;
    const int t4   = lane & 3;
    const int wm   = wid >> 1;
    const int wn   = wid & 1;
    const int row0 = (SWAP ? blockIdx.x : blockIdx.y) * 128;
    const int col0 = (SWAP ? blockIdx.y : blockIdx.x) * BN;
    const int KH   = K >> 1;
    const int NIT  = KH >> 3;

    const int arow  = tid >> 1;
    const int ahalf = tid & 1;
    const int bpl   = tid >> 7;
    const int bkp   = (tid & 127) >> 4;
    const int bq    = tid & 15;

    float acc[2][NTC][4];
    #pragma unroll
    for (int mt = 0; mt < 2; mt++)
        #pragma unroll
        for (int nt = 0; nt < NTC; nt++)
            #pragma unroll
            for (int i = 0; i < 4; i++) acc[mt][nt][i] = 0.f;

    auto issue = [&](int kp0, int buf) {
        cpa16(cvta_s(&As[buf][0][arow][ahalf*4]),
              Ah + (size_t)(row0 + arow)*KH + kp0 + ahalf*4);
        cpa16(cvta_s(&As[buf][1][arow][ahalf*4]),
              Al + (size_t)(row0 + arow)*KH + kp0 + ahalf*4);
        const uint32_t* bp = (bpl ? Bl : Bh) + (size_t)(kp0 + bkp)*NB + col0 + bq*4;
        cpa16(cvta_s(&Bs[buf][bpl][bkp][bq*4]), bp);
        if (NTC == 8)
            cpa16(cvta_s(&Bs[buf][bpl][bkp][bq*4 + 64]), bp + 64);
    };

    issue(0, 0);
    CP_COMMIT();

    for (int it = 0; it < NIT; it++) {
        int cur = it & 1;
        if (it + 1 < NIT) {
            issue((it + 1) * 8, cur ^ 1);
            CP_COMMIT();
            CP_WAIT(1);
        } else {
            CP_WAIT(0);
        }
        __syncthreads();

        uint32_t ah[2][4], al[2][4];
        #pragma unroll
        for (int mt = 0; mt < 2; mt++) {
            int rb = wm*32 + mt*16;
            ah[mt][0] = As[cur][0][rb + g    ][t4    ];
            ah[mt][1] = As[cur][0][rb + g + 8][t4    ];
            ah[mt][2] = As[cur][0][rb + g    ][t4 + 4];
            ah[mt][3] = As[cur][0][rb + g + 8][t4 + 4];
            al[mt][0] = As[cur][1][rb + g    ][t4    ];
            al[mt][1] = As[cur][1][rb + g + 8][t4    ];
            al[mt][2] = As[cur][1][rb + g    ][t4 + 4];
            al[mt][3] = As[cur][1][rb + g + 8][t4 + 4];
        }
        #pragma unroll
        for (int nt = 0; nt < NTC; nt++) {
            int cb = wn*(NTC*8) + nt*8 + g;
            uint32_t bh0 = Bs[cur][0][t4    ][cb];
            uint32_t bh1 = Bs[cur][0][t4 + 4][cb];
            uint32_t bl0 = Bs[cur][1][t4    ][cb];
            uint32_t bl1 = Bs[cur][1][t4 + 4][cb];
            #pragma unroll
            for (int mt = 0; mt < 2; mt++) {
                mma_bf16(acc[mt][nt], ah[mt], bh0, bh1);
                mma_bf16(acc[mt][nt], ah[mt], bl0, bl1);
                mma_bf16(acc[mt][nt], al[mt], bh0, bh1);
            }
        }
        __syncthreads();
    }

    #pragma unroll
    for (int mt = 0; mt < 2; mt++) {
        #pragma unroll
        for (int nt = 0; nt < NTC; nt++) {
            float vv[4];
            #pragma unroll
            for (int i = 0; i < 4; i++) {
                int col = col0 + wn*(NTC*8) + nt*8 + 2*t4 + (i & 1);
                float v = acc[mt][nt][i];
                if (bias && col < N) v += bias[col];
                if (ACT == 1) v = 0.5f * v * (1.f + erff(v * 0.70710678118654752f));
                vv[i] = v;
            }
            #pragma unroll
            for (int i = 0; i < 4; i++) {
                int row = row0 + wm*32 + mt*16 + g + (i >> 1)*8;
                int col = col0 + wn*(NTC*8) + nt*8 + 2*t4 + (i & 1);
                if (col >= N) continue;
                float v = vv[i];
                if (R) v += R[(size_t)row*N + col];
                C[(size_t)row*N + col] = v;
            }
            if (PACK) {
                int cp = (col0 >> 1) + wn*(NTC*4) + nt*4 + t4;
                int NH = N >> 1;
                uint32_t h, l;
                int r0p = row0 + wm*32 + mt*16 + g;
                split_pack(vv[0], vv[1], h, l);
                Ph[(size_t)r0p*NH + cp] = h;  Pl[(size_t)r0p*NH + cp] = l;
                split_pack(vv[2], vv[3], h, l);
                Ph[(size_t)(r0p + 8)*NH + cp] = h;  Pl[(size_t)(r0p + 8)*NH + cp] = l;
            }
        }
    }
}

// ---------------- flash attention (packed-z output) ----------------
#define KT 64
__global__ __launch_bounds__(128)
void attn_flash_kernel(const float* __restrict__ qkv,
                       uint32_t* __restrict__ Zh,
                       uint32_t* __restrict__ Zl) {
    const int qt  = (gridDim.x - 1) - blockIdx.x;
    const int h   = blockIdx.y;
    const int tid = threadIdx.x;
    const int q   = qt*128 + tid;
    const int qmax = qt*128 + 127;

    __shared__ unsigned long long Ks[KT][33];
    __shared__ unsigned long long Vs[KT][33];

    unsigned long long qp[32];
    {
        const float4* qrow = reinterpret_cast<const float4*>(
            qkv + (size_t)q*QKVN + h*DH);
        #pragma unroll
        for (int i = 0; i < 16; i++) {
            float4 v = qrow[i];
            qp[2*i]   = pk2(v.x, v.y);
            qp[2*i+1] = pk2(v.z, v.w);
        }
    }
    unsigned long long accp[32];
    #pragma unroll
    for (int i = 0; i < 32; i++) accp[i] = 0ULL;
    float m = -1e30f, lsum = 0.f;

    const int row  = tid >> 1;
    const int half = tid & 1;

    for (int t0 = 0; t0 <= qmax; t0 += KT) {
        __syncthreads();
        {
            const float4* ksrc = reinterpret_cast<const float4*>(
                qkv + (size_t)(t0 + row)*QKVN + DM + h*DH + half*32);
            const float4* vsrc = reinterpret_cast<const float4*>(
                qkv + (size_t)(t0 + row)*QKVN + 2*DM + h*DH + half*32);
            #pragma unroll
            for (int j = 0; j < 8; j++) {
                float4 kv = ksrc[j];
                Ks[row][half*16 + 2*j]     = pk2(kv.x, kv.y);
                Ks[row][half*16 + 2*j + 1] = pk2(kv.z, kv.w);
                float4 vvv = vsrc[j];
                Vs[row][half*16 + 2*j]     = pk2(vvv.x, vvv.y);
                Vs[row][half*16 + 2*j + 1] = pk2(vvv.z, vvv.w);
            }
        }
        __syncthreads();

        int len = q + 1 - t0;
        if (len > KT) len = KT;
        for (int t = 0; t < len; t++) {
            const unsigned long long* kr = Ks[t];
            unsigned long long d0 = 0ULL, d1 = 0ULL, d2 = 0ULL, d3 = 0ULL;
            #pragma unroll
            for (int i = 0; i < 8; i++) {
                d0 = fma2(qp[4*i    ], kr[4*i    ], d0);
                d1 = fma2(qp[4*i + 1], kr[4*i + 1], d1);
                d2 = fma2(qp[4*i + 2], kr[4*i + 2], d2);
                d3 = fma2(qp[4*i + 3], kr[4*i + 3], d3);
            }
            float a0, a1, b0, b1, c0, c1, e0, e1;
            unpk2(d0, a0, a1); unpk2(d1, b0, b1);
            unpk2(d2, c0, c1); unpk2(d3, e0, e1);
            float sc = ((a0 + a1) + (b0 + b1)) + ((c0 + c1) + (e0 + e1));
            sc *= 0.125f;

            float p;
            if (sc > m) {
                float r = __expf(m - sc);
                unsigned long long r2 = pk2(r, r);
                #pragma unroll
                for (int i = 0; i < 32; i++) accp[i] = mul2(accp[i], r2);
                lsum *= r;
                m = sc;
                p = 1.f;
            } else {
                p = __expf(sc - m);
            }
            lsum += p;
            unsigned long long pp = pk2(p, p);
            const unsigned long long* vr = Vs[t];
            #pragma unroll
            for (int i = 0; i < 32; i++)
                accp[i] = fma2(pp, vr[i], accp[i]);
        }
    }

    float inv = 1.f / lsum;
    #pragma unroll
    for (int i = 0; i < 32; i++) {
        float x0, x1;
        unpk2(accp[i], x0, x1);
        uint32_t hh, ll;
        split_pack(x0 * inv, x1 * inv, hh, ll);
        Zh[(size_t)q*KH_DM + h*32 + i] = hh;
        Zl[(size_t)q*KH_DM + h*32 + i] = ll;
    }
}

// ---------------- plain copy ----------------
__global__ void copy_kernel(const float* __restrict__ src, float* __restrict__ dst, int n) {
    int i = blockIdx.x * 256 + threadIdx.x;
    if (i < n) dst[i] = src[i];
}

// ---------------- launcher ----------------
extern "C" void kernel_launch(void* const* d_in, const int* in_sizes, int n_in,
                              void* d_out, int out_size) {
    const int*   tokens = (const int*)  d_in[0];
    const float* W_E    = (const float*)d_in[1];
    const float* W_pos  = (const float*)d_in[2];
    const float* ln1_w  = (const float*)d_in[3];
    const float* ln1_b  = (const float*)d_in[4];
    const float* W_Q    = (const float*)d_in[5];
    const float* b_Q    = (const float*)d_in[6];
    const float* W_K    = (const float*)d_in[7];
    const float* b_K    = (const float*)d_in[8];
    const float* W_V    = (const float*)d_in[9];
    const float* b_V    = (const float*)d_in[10];
    const float* W_O    = (const float*)d_in[11];
    const float* b_O    = (const float*)d_in[12];
    const float* ln2_w  = (const float*)d_in[13];
    const float* ln2_b  = (const float*)d_in[14];
    const float* W_in   = (const float*)d_in[15];
    const float* b_in   = (const float*)d_in[16];
    const float* W_out  = (const float*)d_in[17];
    const float* b_out  = (const float*)d_in[18];
    const float* lnf_w  = (const float*)d_in[19];
    const float* lnf_b  = (const float*)d_in[20];
    const float* W_U    = (const float*)d_in[21];
    const float* b_U    = (const float*)d_in[22];

    float *p_resid, *p_qkv, *p_post, *p_bqkv;
    cudaGetSymbolAddress((void**)&p_resid, g_resid);
    cudaGetSymbolAddress((void**)&p_qkv,   g_qkv);
    cudaGetSymbolAddress((void**)&p_post,  g_post);
    cudaGetSymbolAddress((void**)&p_bqkv,  g_bqkv);

    uint32_t *pxh, *pxl, *pzh, *pzl, *pph, *ppl;
    cudaGetSymbolAddress((void**)&pxh, a_x_h); cudaGetSymbolAddress((void**)&pxl, a_x_l);
    cudaGetSymbolAddress((void**)&pzh, a_z_h); cudaGetSymbolAddress((void**)&pzl, a_z_l);
    cudaGetSymbolAddress((void**)&pph, a_p_h); cudaGetSymbolAddress((void**)&ppl, a_p_l);

    uint32_t *pwqh, *pwql, *pwoh, *pwol, *pwih, *pwil, *pw2h, *pw2l, *pwUh, *pwUl;
    cudaGetSymbolAddress((void**)&pwqh, wqkv_h); cudaGetSymbolAddress((void**)&pwql, wqkv_l);
    cudaGetSymbolAddress((void**)&pwoh, wo_h);   cudaGetSymbolAddress((void**)&pwol, wo_l);
    cudaGetSymbolAddress((void**)&pwih, wi_h);   cudaGetSymbolAddress((void**)&pwil, wi_l);
    cudaGetSymbolAddress((void**)&pw2h, wu2_h);  cudaGetSymbolAddress((void**)&pw2l, wu2_l);
    cudaGetSymbolAddress((void**)&pwUh, wU_h);   cudaGetSymbolAddress((void**)&pwUl, wU_l);

    float* out = (float*)d_out;

    embed_kernel<<<(S*DM + 255)/256, 256>>>(tokens, W_E, W_pos, p_resid);

    // ---- one-time weight conversions (per launch) ----
    for (int l = 0; l < L; l++) {
        pack_qkv_kernel<<<(KH_DM*DM + 255)/256, 256>>>(
            W_Q + (size_t)l*H*DM*DH, W_K + (size_t)l*H*DM*DH, W_V + (size_t)l*H*DM*DH,
            b_Q + (size_t)l*H*DH, b_K + (size_t)l*H*DH, b_V + (size_t)l*H*DH,
            pwqh + (size_t)l*KH_DM*QKVN, pwql + (size_t)l*KH_DM*QKVN,
            p_bqkv + (size_t)l*QKVN);
        long long t;
        t = (long long)KH_DM*(DM/4);
        convert_w4_kernel<<<(int)((t + 255)/256), 256>>>(
            W_O + (size_t)l*H*DH*DM,
            pwoh + (size_t)l*KH_DM*DM, pwol + (size_t)l*KH_DM*DM, DM, DM);
        t = (long long)KH_DM*(DMLP/4);
        convert_w4_kernel<<<(int)((t + 255)/256), 256>>>(
            W_in + (size_t)l*DM*DMLP,
            pwih + (size_t)l*KH_DM*DMLP, pwil + (size_t)l*KH_DM*DMLP, DM, DMLP);
        t = (long long)KH_MLP*(DM/4);
        convert_w4_kernel<<<(int)((t + 255)/256), 256>>>(
            W_out + (size_t)l*DMLP*DM,
            pw2h + (size_t)l*KH_MLP*DM, pw2l + (size_t)l*KH_MLP*DM, DMLP, DM);
    }
    {
        long long t = (long long)KH_DM*(NVP/4);
        convert_wu_kernel<<<(int)((t + 255)/256), 256>>>(W_U, pwUh, pwUl, DM, NV, NVP);
    }

    for (int l = 0; l < L; l++) {
        const float* bo  = b_O   + (size_t)l*DM;
        const float* l1w = ln1_w + (size_t)l*DM, *l1b = ln1_b + (size_t)l*DM;
        const float* l2w = ln2_w + (size_t)l*DM, *l2b = ln2_b + (size_t)l*DM;
        const float* bi  = b_in  + (size_t)l*DMLP;
        const float* bo2 = b_out + (size_t)l*DM;

        ln_pack_kernel<<<S, 256>>>(p_resid, l1w, l1b, pxh, pxl);

        // qkv = x @ wqkv + bqkv   (wide tile)
        bf16_gemm_kernel<0,0,8,0><<<dim3(QKVN/128, S/128), 256>>>(
            pxh, pxl, pwqh + (size_t)l*KH_DM*QKVN, pwql + (size_t)l*KH_DM*QKVN,
            p_bqkv + (size_t)l*QKVN, nullptr, p_qkv, nullptr, nullptr,
            QKVN, QKVN, DM);

        attn_flash_kernel<<<dim3(S/128, H), 128>>>(p_qkv, pzh, pzl);

        // resid += z @ W_O + b_O
        bf16_gemm_kernel<0,0,4,0><<<dim3(DM/64, S/128), 256>>>(
            pzh, pzl, pwoh + (size_t)l*KH_DM*DM, pwol + (size_t)l*KH_DM*DM,
            bo, p_resid, p_resid, nullptr, nullptr, DM, DM, DM);

        ln_pack_kernel<<<S, 256>>>(p_resid, l2w, l2b, pxh, pxl);

        // post = gelu(x @ W_in + b_in)  (wide tile; float + packed planes)
        bf16_gemm_kernel<1,1,8,0><<<dim3(DMLP/128, S/128), 256>>>(
            pxh, pxl, pwih + (size_t)l*KH_DM*DMLP, pwil + (size_t)l*KH_DM*DMLP,
            bi, nullptr, p_post, pph, ppl, DMLP, DMLP, DM);

        // resid += post @ W_out + b_out
        bf16_gemm_kernel<0,0,4,0><<<dim3(DM/64, S/128), 256>>>(
            pph, ppl, pw2h + (size_t)l*KH_MLP*DM, pw2l + (size_t)l*KH_MLP*DM,
            bo2, p_resid, p_resid, nullptr, nullptr, DM, DM, DMLP);
    }

    ln_pack_kernel<<<S, 256>>>(p_resid, lnf_w, lnf_b, pxh, pxl);
    // unembed: SWAP grid (x=rows) so the 16 row-blocks sharing each 512KB
    // B column tile are co-resident -> B read once from DRAM, 15x from L2.
    bf16_gemm_kernel<0,0,8,1><<<dim3(S/128, NVP/128), 256>>>(
        pxh, pxl, pwUh, pwUl, b_U, nullptr, out, nullptr, nullptr,
        NV, NVP, DM);

    const long long LOG_N  = (long long)S * NV;
    const long long RES_N  = (long long)S * DM;
    const long long POST_N = (long long)S * DMLP;
    long long osz = (long long)out_size;
    if (osz >= LOG_N + RES_N)
        copy_kernel<<<(int)((RES_N + 255)/256), 256>>>(p_resid, out + LOG_N, (int)RES_N);
    if (osz >= LOG_N + RES_N + POST_N)
        copy_kernel<<<(int)((POST_N + 255)/256), 256>>>(p_post, out + LOG_N + RES_N, (int)POST_N);
}